// round 2
// baseline (speedup 1.0000x reference)
#include <cuda_runtime.h>

#define DIM 128
#define N_TOTAL 299593

// Level sizes/offsets for B=8, L=7 perfect tree
static const int H_SIZES[7] = {1, 8, 64, 512, 4096, 32768, 262144};
static const int H_OFFS[8]  = {0, 1, 9, 73, 585, 4681, 37449, 299593};

// ---------------- scratch (device globals; no allocations allowed) ----------------
__device__ float g_agg[N_TOTAL * DIM];        // agg vec for every node (153 MB)
__device__ float g_ctx[N_TOTAL * DIM];        // ctx vec for every node (153 MB)
__device__ float g_h  [262144 * DIM];         // per-level GEMM output tmp (134 MB)
__device__ float g_t2 [ 65536 * DIM];         // per-level small tmp (34 MB)

// ---------------- GEMM: Y[M,128] = relu(X[M,K] @ W[128,K]^T + b) ----------------
// Block: 128 threads = 4 warps, 32 rows per block (8 rows per warp).
// W staged in smem as float4 per k: sW[k][lane] = {W[lane][k],W[lane+32][k],W[lane+64][k],W[lane+96][k]}
// X rows staged in smem, accessed as warp-broadcast.
template <int K>
__global__ void __launch_bounds__(128) gemm_relu_k(
    const float* __restrict__ X, const float* __restrict__ W,
    const float* __restrict__ bias, float* __restrict__ Y, int M)
{
    extern __shared__ float smem[];
    float4* sW = reinterpret_cast<float4*>(smem);   // K*32 float4 = K*128 floats
    float*  sX = smem + K * 128;                    // 32 * K floats

    const int tid = threadIdx.x;

    // stage W (transposed/interleaved)
    for (int i = tid; i < 128 * K; i += 128) {
        int e = i / K, k = i - e * K;
        smem[(k * 32 + (e & 31)) * 4 + (e >> 5)] = W[i];
    }
    // stage X tile (zero-padded past M)
    const int row0 = blockIdx.x * 32;
    for (int i = tid; i < 32 * K; i += 128) {
        int r = i / K, k = i - r * K;
        int gr = row0 + r;
        sX[i] = (gr < M) ? X[(long)gr * K + k] : 0.0f;
    }
    __syncthreads();

    const int lane = tid & 31, warp = tid >> 5;
    const float* xb = sX + (warp * 8) * K;

    float4 acc[8];
#pragma unroll
    for (int r = 0; r < 8; r++) acc[r] = make_float4(0.f, 0.f, 0.f, 0.f);

#pragma unroll 4
    for (int k = 0; k < K; k++) {
        float4 w = sW[k * 32 + lane];
#pragma unroll
        for (int r = 0; r < 8; r++) {
            float x = xb[r * K + k];
            acc[r].x += x * w.x; acc[r].y += x * w.y;
            acc[r].z += x * w.z; acc[r].w += x * w.w;
        }
    }

    float4 b = make_float4(bias[lane], bias[lane + 32], bias[lane + 64], bias[lane + 96]);
#pragma unroll
    for (int r = 0; r < 8; r++) {
        int gr = row0 + warp * 8 + r;
        if (gr < M) {
            float* y = Y + (long)gr * 128;
            y[lane]      = fmaxf(acc[r].x + b.x, 0.f);
            y[lane + 32] = fmaxf(acc[r].y + b.y, 0.f);
            y[lane + 64] = fmaxf(acc[r].z + b.z, 0.f);
            y[lane + 96] = fmaxf(acc[r].w + b.w, 0.f);
        }
    }
}

// ---------------- fused final: out[i] = bh + Wh . relu(Wf @ [ctx_i; agg_i] + bf) ----------------
__global__ void __launch_bounds__(128) final_fused(
    const float* __restrict__ CTX, const float* __restrict__ AGG,
    const float* __restrict__ Wf, const float* __restrict__ bf,
    const float* __restrict__ Wh, const float* __restrict__ bh,
    float* __restrict__ out, int M)
{
    const int K = 256;
    extern __shared__ float smem[];
    float4* sW = reinterpret_cast<float4*>(smem);
    float*  sX = smem + K * 128;

    const int tid = threadIdx.x;
    for (int i = tid; i < 128 * K; i += 128) {
        int e = i / K, k = i - e * K;
        smem[(k * 32 + (e & 31)) * 4 + (e >> 5)] = Wf[i];
    }
    const int row0 = blockIdx.x * 32;
    for (int i = tid; i < 32 * K; i += 128) {
        int r = i >> 8, k = i & 255;
        int gr = row0 + r;
        float v = 0.f;
        if (gr < M) v = (k < 128) ? CTX[(long)gr * 128 + k] : AGG[(long)gr * 128 + (k - 128)];
        sX[i] = v;
    }
    __syncthreads();

    const int lane = tid & 31, warp = tid >> 5;
    const float* xb = sX + (warp * 8) * K;

    float4 acc[8];
#pragma unroll
    for (int r = 0; r < 8; r++) acc[r] = make_float4(0.f, 0.f, 0.f, 0.f);

#pragma unroll 4
    for (int k = 0; k < K; k++) {
        float4 w = sW[k * 32 + lane];
#pragma unroll
        for (int r = 0; r < 8; r++) {
            float x = xb[r * K + k];
            acc[r].x += x * w.x; acc[r].y += x * w.y;
            acc[r].z += x * w.z; acc[r].w += x * w.w;
        }
    }

    float4 b  = make_float4(bf[lane], bf[lane + 32], bf[lane + 64], bf[lane + 96]);
    float4 wh = make_float4(Wh[lane], Wh[lane + 32], Wh[lane + 64], Wh[lane + 96]);
    float  bhv = bh[0];
#pragma unroll
    for (int r = 0; r < 8; r++) {
        int gr = row0 + warp * 8 + r;
        float v = fmaxf(acc[r].x + b.x, 0.f) * wh.x
                + fmaxf(acc[r].y + b.y, 0.f) * wh.y
                + fmaxf(acc[r].z + b.z, 0.f) * wh.z
                + fmaxf(acc[r].w + b.w, 0.f) * wh.w;
#pragma unroll
        for (int o = 16; o > 0; o >>= 1) v += __shfl_down_sync(0xffffffffu, v, o);
        if (lane == 0 && gr < M) out[gr] = v + bhv;
    }
}

// ---------------- elementwise helpers ----------------
__device__ __forceinline__ float4 f4add(float4 a, float4 b) {
    return make_float4(a.x + b.x, a.y + b.y, a.z + b.z, a.w + b.w);
}
__device__ __forceinline__ float4 f4sub(float4 a, float4 b) {
    return make_float4(a.x - b.x, a.y - b.y, a.z - b.z, a.w - b.w);
}
__device__ __forceinline__ float4 f4scale(float4 a, float s) {
    return make_float4(a.x * s, a.y * s, a.z * s, a.w * s);
}

// mean over groups of 4 consecutive rows: out[g] = 0.25 * sum_{s<4} in[4g+s]
__global__ void reduce4_mean(const float4* __restrict__ in, float4* __restrict__ out, int Gtot)
{
    int idx = blockIdx.x * blockDim.x + threadIdx.x;
    int tot = Gtot * 32;
    if (idx >= tot) return;
    int g = idx >> 5, c = idx & 31;
    float4 a = in[(g * 4 + 0) * 32 + c];
    float4 b = in[(g * 4 + 1) * 32 + c];
    float4 d = in[(g * 4 + 2) * 32 + c];
    float4 e = in[(g * 4 + 3) * 32 + c];
    out[g * 32 + c] = f4scale(f4add(f4add(a, b), f4add(d, e)), 0.25f);
}

// out[g] = init[g] + 0.5*(in[2g] + in[2g+1])    (EPS = 1, T = 2)
__global__ void reduce2_mean_add(const float4* __restrict__ in, const float4* __restrict__ init,
                                 float4* __restrict__ out, int Gtot)
{
    int idx = blockIdx.x * blockDim.x + threadIdx.x;
    int tot = Gtot * 32;
    if (idx >= tot) return;
    int g = idx >> 5, c = idx & 31;
    float4 a = in[(g * 2 + 0) * 32 + c];
    float4 b = in[(g * 2 + 1) * 32 + c];
    float4 i0 = init[g * 32 + c];
    out[g * 32 + c] = f4add(i0, f4scale(f4add(a, b), 0.5f));
}

// down-pass context distribution; g indexes (node, tactic) groups, Gtot = SIZES[l]*T
// out[4g+s] = (cth[g/2] + sum_{s'} hx[4g+s'] - hx[4g+s]) / 4
__global__ void combine_ctx(const float4* __restrict__ hx, const float4* __restrict__ cth,
                            float4* __restrict__ out, int Gtot)
{
    int idx = blockIdx.x * blockDim.x + threadIdx.x;
    int tot = Gtot * 32;
    if (idx >= tot) return;
    int g = idx >> 5, c = idx & 31;
    int n = g >> 1;
    float4 h0 = hx[(g * 4 + 0) * 32 + c];
    float4 h1 = hx[(g * 4 + 1) * 32 + c];
    float4 h2 = hx[(g * 4 + 2) * 32 + c];
    float4 h3 = hx[(g * 4 + 3) * 32 + c];
    float4 cv = cth[n * 32 + c];
    float4 tot4 = f4add(cv, f4add(f4add(h0, h1), f4add(h2, h3)));
    out[(g * 4 + 0) * 32 + c] = f4scale(f4sub(tot4, h0), 0.25f);
    out[(g * 4 + 1) * 32 + c] = f4scale(f4sub(tot4, h1), 0.25f);
    out[(g * 4 + 2) * 32 + c] = f4scale(f4sub(tot4, h2), 0.25f);
    out[(g * 4 + 3) * 32 + c] = f4scale(f4sub(tot4, h3), 0.25f);
}

__global__ void set_ones(float* p, int n)
{
    int i = blockIdx.x * blockDim.x + threadIdx.x;
    if (i < n) p[i] = 1.0f;
}

__global__ void copy_f4(float4* __restrict__ dst, const float4* __restrict__ src, long n4)
{
    long i = (long)blockIdx.x * blockDim.x + threadIdx.x;
    long stride = (long)gridDim.x * blockDim.x;
    for (; i < n4; i += stride) dst[i] = src[i];
}

// ---------------- launch ----------------
extern "C" void kernel_launch(void* const* d_in, const int* in_sizes, int n_in,
                              void* d_out, int out_size)
{
    const float* initial = (const float*)d_in[0];
    const float* Ws = (const float*)d_in[1];
    const float* bs = (const float*)d_in[2];
    const float* Wc = (const float*)d_in[3];
    const float* bc = (const float*)d_in[4];
    const float* Wx = (const float*)d_in[5];
    const float* bx = (const float*)d_in[6];
    const float* Wf = (const float*)d_in[7];
    const float* bf = (const float*)d_in[8];
    const float* Wh = (const float*)d_in[9];
    const float* bh = (const float*)d_in[10];
    float* out = (float*)d_out;

    float *p_agg, *p_ctx, *p_h, *p_t2;
    cudaGetSymbolAddress((void**)&p_agg, g_agg);
    cudaGetSymbolAddress((void**)&p_ctx, g_ctx);
    cudaGetSymbolAddress((void**)&p_h,   g_h);
    cudaGetSymbolAddress((void**)&p_t2,  g_t2);

    const int SMEM128 = (128 * 128 + 32 * 128) * 4;   //  80 KB
    const int SMEM256 = (256 * 128 + 32 * 256) * 4;   // 160 KB
    cudaFuncSetAttribute(gemm_relu_k<128>, cudaFuncAttributeMaxDynamicSharedMemorySize, SMEM128);
    cudaFuncSetAttribute(final_fused,      cudaFuncAttributeMaxDynamicSharedMemorySize, SMEM256);

    // leaves: agg = initial
    {
        long n4 = (long)H_SIZES[6] * DIM / 4;
        copy_f4<<<4096, 256>>>((float4*)(p_agg + (long)H_OFFS[6] * DIM),
                               (const float4*)(initial + (long)H_OFFS[6] * DIM), n4);
    }

    // ---- up pass ----
    for (int l = 5; l >= 0; l--) {
        int M1 = H_SIZES[l + 1];              // children rows
        int G  = H_SIZES[l] * 2;              // (node,tactic) groups
        int Ml = H_SIZES[l];

        gemm_relu_k<128><<<(M1 + 31) / 32, 128, SMEM128>>>(
            p_agg + (long)H_OFFS[l + 1] * DIM, Ws, bs, p_h, M1);

        {
            int tot = G * 32;
            reduce4_mean<<<(tot + 255) / 256, 256>>>((const float4*)p_h, (float4*)p_t2, G);
        }

        gemm_relu_k<128><<<(G + 31) / 32, 128, SMEM128>>>(p_t2, Wc, bc, p_h, G);

        {
            int tot = Ml * 32;
            reduce2_mean_add<<<(tot + 255) / 256, 256>>>(
                (const float4*)p_h,
                (const float4*)(initial + (long)H_OFFS[l] * DIM),
                (float4*)(p_agg + (long)H_OFFS[l] * DIM), Ml);
        }
    }

    // ---- down pass ----
    set_ones<<<1, 128>>>(p_ctx, DIM);   // root ctx = ones
    for (int l = 0; l < 6; l++) {
        int M1 = H_SIZES[l + 1];
        int Ml = H_SIZES[l];
        int G  = Ml * 2;

        gemm_relu_k<128><<<(M1 + 31) / 32, 128, SMEM128>>>(
            p_agg + (long)H_OFFS[l + 1] * DIM, Wx, bx, p_h, M1);
        gemm_relu_k<128><<<(Ml + 31) / 32, 128, SMEM128>>>(
            p_ctx + (long)H_OFFS[l] * DIM, Wx, bx, p_t2, Ml);

        int tot = G * 32;
        combine_ctx<<<(tot + 255) / 256, 256>>>(
            (const float4*)p_h, (const float4*)p_t2,
            (float4*)(p_ctx + (long)H_OFFS[l + 1] * DIM), G);
    }

    // ---- final: fused [ctx|agg] @ Wf^T -> relu -> . Wh + bh ----
    final_fused<<<(N_TOTAL + 31) / 32, 128, SMEM256>>>(
        p_ctx, p_agg, Wf, bf, Wh, bh, out, N_TOTAL);
}

// round 3
// speedup vs baseline: 3.8615x; 3.8615x over previous
#include <cuda_runtime.h>
#include <cuda_bf16.h>

#define DIM 128
#define N_TOTAL 299593

// Level sizes/offsets for B=8, L=7 perfect tree
static const int H_SIZES[7] = {1, 8, 64, 512, 4096, 32768, 262144};
static const int H_OFFS[8]  = {0, 1, 9, 73, 585, 4681, 37449, 299593};

// ---------------- scratch (device globals; no allocations allowed) ----------------
__device__ float g_agg[N_TOTAL * DIM];
__device__ float g_ctx[N_TOTAL * DIM];
__device__ float g_h  [262144 * DIM];
__device__ float g_t2 [ 65536 * DIM];

// ================= bf16x3 tensor-core GEMM =================
// Y[M,128] = relu(X[M,K] @ W[128,K]^T + bias), split-precision bf16 (hi+lo),
// 3 MMA passes: hi*hi + hi*lo + lo*hi  (lo*lo dropped, ~2^-18 relative).
//
// Block: 256 threads = 8 warps. Tile: 128 rows x 128 cols. Warp w owns rows
// [w*16, w*16+16). smem: W and X tiles as bf16 hi/lo, row stride 136 (pad 8)
// -> all fragment loads bank-conflict-free.

#define SPITCH 136
#define STILE  (128 * SPITCH)

__device__ __forceinline__ void mma16816(float* c, const unsigned* a,
                                         unsigned b0, unsigned b1)
{
    asm volatile(
        "mma.sync.aligned.m16n8k16.row.col.f32.bf16.bf16.f32 "
        "{%0,%1,%2,%3},{%4,%5,%6,%7},{%8,%9},{%0,%1,%2,%3};\n"
        : "+f"(c[0]), "+f"(c[1]), "+f"(c[2]), "+f"(c[3])
        : "r"(a[0]), "r"(a[1]), "r"(a[2]), "r"(a[3]), "r"(b0), "r"(b1));
}

// Stage a 128x128 fp32 tile from G (rows < rows_valid; gstride floats/row)
// into shi/slo as bf16 hi/lo, row pitch SPITCH.
__device__ __forceinline__ void stage_tile(
    const float* __restrict__ G, int rows_valid, int gstride,
    __nv_bfloat16* shi, __nv_bfloat16* slo, int tid)
{
    for (int idx = tid; idx < 128 * 32; idx += 256) {
        int r = idx >> 5, c4 = (idx & 31) * 4;
        float4 v = make_float4(0.f, 0.f, 0.f, 0.f);
        if (r < rows_valid) v = *(const float4*)(G + (size_t)r * gstride + c4);

        __nv_bfloat16 h0 = __float2bfloat16(v.x);
        __nv_bfloat16 h1 = __float2bfloat16(v.y);
        __nv_bfloat16 h2 = __float2bfloat16(v.z);
        __nv_bfloat16 h3 = __float2bfloat16(v.w);
        __nv_bfloat16 l0 = __float2bfloat16(v.x - __bfloat162float(h0));
        __nv_bfloat16 l1 = __float2bfloat16(v.y - __bfloat162float(h1));
        __nv_bfloat16 l2 = __float2bfloat16(v.z - __bfloat162float(h2));
        __nv_bfloat16 l3 = __float2bfloat16(v.w - __bfloat162float(h3));

        uint2 hv, lv;
        hv.x = ((unsigned)__bfloat16_as_ushort(h1) << 16) | __bfloat16_as_ushort(h0);
        hv.y = ((unsigned)__bfloat16_as_ushort(h3) << 16) | __bfloat16_as_ushort(h2);
        lv.x = ((unsigned)__bfloat16_as_ushort(l1) << 16) | __bfloat16_as_ushort(l0);
        lv.y = ((unsigned)__bfloat16_as_ushort(l3) << 16) | __bfloat16_as_ushort(l2);
        *(uint2*)(shi + (size_t)r * SPITCH + c4) = hv;
        *(uint2*)(slo + (size_t)r * SPITCH + c4) = lv;
    }
}

// Shared mainloop: accumulate one 128-wide k-panel into C[16][4].
__device__ __forceinline__ void panel_mma(
    const __nv_bfloat16* sWhi, const __nv_bfloat16* sWlo,
    const __nv_bfloat16* sXhi, const __nv_bfloat16* sXlo,
    int warp, int g, int tg, float C[16][4])
{
    const int arow = warp * 16 + g;
#pragma unroll
    for (int kc = 0; kc < 8; kc++) {
        const int ko = kc * 16 + tg * 2;
        const __nv_bfloat16* pa = sXhi + arow * SPITCH + ko;
        const __nv_bfloat16* pl = sXlo + arow * SPITCH + ko;
        unsigned ah[4], al[4];
        ah[0] = *(const unsigned*)(pa);
        ah[1] = *(const unsigned*)(pa + 8 * SPITCH);
        ah[2] = *(const unsigned*)(pa + 8);
        ah[3] = *(const unsigned*)(pa + 8 * SPITCH + 8);
        al[0] = *(const unsigned*)(pl);
        al[1] = *(const unsigned*)(pl + 8 * SPITCH);
        al[2] = *(const unsigned*)(pl + 8);
        al[3] = *(const unsigned*)(pl + 8 * SPITCH + 8);
#pragma unroll
        for (int t = 0; t < 16; t++) {
            const __nv_bfloat16* pb  = sWhi + (t * 8 + g) * SPITCH + ko;
            const __nv_bfloat16* pbl = sWlo + (t * 8 + g) * SPITCH + ko;
            unsigned bh0 = *(const unsigned*)(pb);
            unsigned bh1 = *(const unsigned*)(pb + 8);
            unsigned bl0 = *(const unsigned*)(pbl);
            unsigned bl1 = *(const unsigned*)(pbl + 8);
            mma16816(C[t], ah, bh0, bh1);
            mma16816(C[t], ah, bl0, bl1);
            mma16816(C[t], al, bh0, bh1);
        }
    }
}

// Y = relu(X[M,K] @ W[128,K]^T + bias), K multiple of 128.
__global__ void __launch_bounds__(256) gemm_bf16x3(
    const float* __restrict__ X, const float* __restrict__ W,
    const float* __restrict__ bias, float* __restrict__ Y, int M, int K)
{
    extern __shared__ __nv_bfloat16 sm[];
    __nv_bfloat16* sWhi = sm;
    __nv_bfloat16* sWlo = sm + STILE;
    __nv_bfloat16* sXhi = sm + 2 * STILE;
    __nv_bfloat16* sXlo = sm + 3 * STILE;

    const int tid = threadIdx.x, lane = tid & 31, warp = tid >> 5;
    const int g = lane >> 2, tg = lane & 3;
    const int row0 = blockIdx.x * 128;

    float C[16][4];
#pragma unroll
    for (int t = 0; t < 16; t++)
#pragma unroll
        for (int j = 0; j < 4; j++) C[t][j] = 0.f;

    for (int p = 0; p < K; p += 128) {
        __syncthreads();
        stage_tile(W + p, 128, K, sWhi, sWlo, tid);
        stage_tile(X + (size_t)row0 * K + p, M - row0, K, sXhi, sXlo, tid);
        __syncthreads();
        panel_mma(sWhi, sWlo, sXhi, sXlo, warp, g, tg, C);
    }

    const int r0 = row0 + warp * 16 + g, r1 = r0 + 8;
#pragma unroll
    for (int t = 0; t < 16; t++) {
        int c = t * 8 + tg * 2;
        float2 bv = *(const float2*)(bias + c);
        if (r0 < M) {
            float2 o = make_float2(fmaxf(C[t][0] + bv.x, 0.f),
                                   fmaxf(C[t][1] + bv.y, 0.f));
            *(float2*)(Y + (size_t)r0 * 128 + c) = o;
        }
        if (r1 < M) {
            float2 o = make_float2(fmaxf(C[t][2] + bv.x, 0.f),
                                   fmaxf(C[t][3] + bv.y, 0.f));
            *(float2*)(Y + (size_t)r1 * 128 + c) = o;
        }
    }
}

// Fused final: out[i] = bh + Wh . relu(Wf @ [ctx_i; agg_i] + bf), K=256.
__global__ void __launch_bounds__(256) final_bf16x3(
    const float* __restrict__ CTX, const float* __restrict__ AGG,
    const float* __restrict__ Wf, const float* __restrict__ bf,
    const float* __restrict__ Wh, const float* __restrict__ bh,
    float* __restrict__ out, int M)
{
    extern __shared__ __nv_bfloat16 sm[];
    __nv_bfloat16* sWhi = sm;
    __nv_bfloat16* sWlo = sm + STILE;
    __nv_bfloat16* sXhi = sm + 2 * STILE;
    __nv_bfloat16* sXlo = sm + 3 * STILE;

    const int tid = threadIdx.x, lane = tid & 31, warp = tid >> 5;
    const int g = lane >> 2, tg = lane & 3;
    const int row0 = blockIdx.x * 128;

    float C[16][4];
#pragma unroll
    for (int t = 0; t < 16; t++)
#pragma unroll
        for (int j = 0; j < 4; j++) C[t][j] = 0.f;

    for (int p = 0; p < 2; p++) {
        __syncthreads();
        stage_tile(Wf + p * 128, 128, 256, sWhi, sWlo, tid);
        const float* Xsrc = (p == 0) ? CTX : AGG;
        stage_tile(Xsrc + (size_t)row0 * 128, M - row0, 128, sXhi, sXlo, tid);
        __syncthreads();
        panel_mma(sWhi, sWlo, sXhi, sXlo, warp, g, tg, C);
    }

    float s0 = 0.f, s1 = 0.f;
#pragma unroll
    for (int t = 0; t < 16; t++) {
        int c = t * 8 + tg * 2;
        float2 bv = *(const float2*)(bf + c);
        float2 wv = *(const float2*)(Wh + c);
        s0 += fmaxf(C[t][0] + bv.x, 0.f) * wv.x + fmaxf(C[t][1] + bv.y, 0.f) * wv.y;
        s1 += fmaxf(C[t][2] + bv.x, 0.f) * wv.x + fmaxf(C[t][3] + bv.y, 0.f) * wv.y;
    }
    s0 += __shfl_xor_sync(0xffffffffu, s0, 1);
    s0 += __shfl_xor_sync(0xffffffffu, s0, 2);
    s1 += __shfl_xor_sync(0xffffffffu, s1, 1);
    s1 += __shfl_xor_sync(0xffffffffu, s1, 2);

    if (tg == 0) {
        const int r0 = row0 + warp * 16 + g, r1 = r0 + 8;
        float bhv = bh[0];
        if (r0 < M) out[r0] = s0 + bhv;
        if (r1 < M) out[r1] = s1 + bhv;
    }
}

// ---------------- elementwise helpers (unchanged) ----------------
__device__ __forceinline__ float4 f4add(float4 a, float4 b) {
    return make_float4(a.x + b.x, a.y + b.y, a.z + b.z, a.w + b.w);
}
__device__ __forceinline__ float4 f4sub(float4 a, float4 b) {
    return make_float4(a.x - b.x, a.y - b.y, a.z - b.z, a.w - b.w);
}
__device__ __forceinline__ float4 f4scale(float4 a, float s) {
    return make_float4(a.x * s, a.y * s, a.z * s, a.w * s);
}

__global__ void reduce4_mean(const float4* __restrict__ in, float4* __restrict__ out, int Gtot)
{
    int idx = blockIdx.x * blockDim.x + threadIdx.x;
    int tot = Gtot * 32;
    if (idx >= tot) return;
    int g = idx >> 5, c = idx & 31;
    float4 a = in[(g * 4 + 0) * 32 + c];
    float4 b = in[(g * 4 + 1) * 32 + c];
    float4 d = in[(g * 4 + 2) * 32 + c];
    float4 e = in[(g * 4 + 3) * 32 + c];
    out[g * 32 + c] = f4scale(f4add(f4add(a, b), f4add(d, e)), 0.25f);
}

__global__ void reduce2_mean_add(const float4* __restrict__ in, const float4* __restrict__ init,
                                 float4* __restrict__ out, int Gtot)
{
    int idx = blockIdx.x * blockDim.x + threadIdx.x;
    int tot = Gtot * 32;
    if (idx >= tot) return;
    int g = idx >> 5, c = idx & 31;
    float4 a = in[(g * 2 + 0) * 32 + c];
    float4 b = in[(g * 2 + 1) * 32 + c];
    float4 i0 = init[g * 32 + c];
    out[g * 32 + c] = f4add(i0, f4scale(f4add(a, b), 0.5f));
}

__global__ void combine_ctx(const float4* __restrict__ hx, const float4* __restrict__ cth,
                            float4* __restrict__ out, int Gtot)
{
    int idx = blockIdx.x * blockDim.x + threadIdx.x;
    int tot = Gtot * 32;
    if (idx >= tot) return;
    int g = idx >> 5, c = idx & 31;
    int n = g >> 1;
    float4 h0 = hx[(g * 4 + 0) * 32 + c];
    float4 h1 = hx[(g * 4 + 1) * 32 + c];
    float4 h2 = hx[(g * 4 + 2) * 32 + c];
    float4 h3 = hx[(g * 4 + 3) * 32 + c];
    float4 cv = cth[n * 32 + c];
    float4 tot4 = f4add(cv, f4add(f4add(h0, h1), f4add(h2, h3)));
    out[(g * 4 + 0) * 32 + c] = f4scale(f4sub(tot4, h0), 0.25f);
    out[(g * 4 + 1) * 32 + c] = f4scale(f4sub(tot4, h1), 0.25f);
    out[(g * 4 + 2) * 32 + c] = f4scale(f4sub(tot4, h2), 0.25f);
    out[(g * 4 + 3) * 32 + c] = f4scale(f4sub(tot4, h3), 0.25f);
}

__global__ void set_ones(float* p, int n)
{
    int i = blockIdx.x * blockDim.x + threadIdx.x;
    if (i < n) p[i] = 1.0f;
}

__global__ void copy_f4(float4* __restrict__ dst, const float4* __restrict__ src, long n4)
{
    long i = (long)blockIdx.x * blockDim.x + threadIdx.x;
    long stride = (long)gridDim.x * blockDim.x;
    for (; i < n4; i += stride) dst[i] = src[i];
}

// ---------------- launch ----------------
extern "C" void kernel_launch(void* const* d_in, const int* in_sizes, int n_in,
                              void* d_out, int out_size)
{
    const float* initial = (const float*)d_in[0];
    const float* Ws = (const float*)d_in[1];
    const float* bs = (const float*)d_in[2];
    const float* Wc = (const float*)d_in[3];
    const float* bc = (const float*)d_in[4];
    const float* Wx = (const float*)d_in[5];
    const float* bx = (const float*)d_in[6];
    const float* Wf = (const float*)d_in[7];
    const float* bf = (const float*)d_in[8];
    const float* Wh = (const float*)d_in[9];
    const float* bh = (const float*)d_in[10];
    float* out = (float*)d_out;

    float *p_agg, *p_ctx, *p_h, *p_t2;
    cudaGetSymbolAddress((void**)&p_agg, g_agg);
    cudaGetSymbolAddress((void**)&p_ctx, g_ctx);
    cudaGetSymbolAddress((void**)&p_h,   g_h);
    cudaGetSymbolAddress((void**)&p_t2,  g_t2);

    const int SMEM_T = 4 * STILE * (int)sizeof(__nv_bfloat16);  // 139264 B
    cudaFuncSetAttribute(gemm_bf16x3,  cudaFuncAttributeMaxDynamicSharedMemorySize, SMEM_T);
    cudaFuncSetAttribute(final_bf16x3, cudaFuncAttributeMaxDynamicSharedMemorySize, SMEM_T);

    // leaves: agg = initial
    {
        long n4 = (long)H_SIZES[6] * DIM / 4;
        copy_f4<<<4096, 256>>>((float4*)(p_agg + (long)H_OFFS[6] * DIM),
                               (const float4*)(initial + (long)H_OFFS[6] * DIM), n4);
    }

    // ---- up pass ----
    for (int l = 5; l >= 0; l--) {
        int M1 = H_SIZES[l + 1];
        int G  = H_SIZES[l] * 2;
        int Ml = H_SIZES[l];

        gemm_bf16x3<<<(M1 + 127) / 128, 256, SMEM_T>>>(
            p_agg + (long)H_OFFS[l + 1] * DIM, Ws, bs, p_h, M1, 128);

        {
            int tot = G * 32;
            reduce4_mean<<<(tot + 255) / 256, 256>>>((const float4*)p_h, (float4*)p_t2, G);
        }

        gemm_bf16x3<<<(G + 127) / 128, 256, SMEM_T>>>(p_t2, Wc, bc, p_h, G, 128);

        {
            int tot = Ml * 32;
            reduce2_mean_add<<<(tot + 255) / 256, 256>>>(
                (const float4*)p_h,
                (const float4*)(initial + (long)H_OFFS[l] * DIM),
                (float4*)(p_agg + (long)H_OFFS[l] * DIM), Ml);
        }
    }

    // ---- down pass ----
    set_ones<<<1, 128>>>(p_ctx, DIM);
    for (int l = 0; l < 6; l++) {
        int M1 = H_SIZES[l + 1];
        int Ml = H_SIZES[l];
        int G  = Ml * 2;

        gemm_bf16x3<<<(M1 + 127) / 128, 256, SMEM_T>>>(
            p_agg + (long)H_OFFS[l + 1] * DIM, Wx, bx, p_h, M1, 128);
        gemm_bf16x3<<<(Ml + 127) / 128, 256, SMEM_T>>>(
            p_ctx + (long)H_OFFS[l] * DIM, Wx, bx, p_t2, Ml, 128);

        int tot = G * 32;
        combine_ctx<<<(tot + 255) / 256, 256>>>(
            (const float4*)p_h, (const float4*)p_t2,
            (float4*)(p_ctx + (long)H_OFFS[l + 1] * DIM), G);
    }

    // ---- final: fused [ctx|agg] @ Wf^T -> relu -> . Wh + bh ----
    final_bf16x3<<<(N_TOTAL + 127) / 128, 256, SMEM_T>>>(
        p_ctx, p_agg, Wf, bf, Wh, bh, out, N_TOTAL);
}